// round 3
// baseline (speedup 1.0000x reference)
#include <cuda_runtime.h>
#include <math.h>

#define L_LEN   100000
#define B_ROWS  512
#define HALF    50000          // L/2 pooled elements per row
#define QOUT    (HALF / 2)     // 25000 float4 outputs per row
#define NOISE_STD 0.04f
#define NTHREADS 1024
#define UNROLL  4

// Precomputed per-position noise contribution to each pooled element:
// npool[j] = (noise[2j] + noise[2j+1]) * STD / 2. Row-invariant, L2-resident.
__device__ float g_npool[HALF];

__global__ void noise_pool_kernel(const float* __restrict__ noise) {
    int j = blockIdx.x * blockDim.x + threadIdx.x;
    if (j < HALF) {
        float2 n = reinterpret_cast<const float2*>(noise)[j];
        g_npool[j] = (n.x + n.y) * (0.5f * NOISE_STD);
    }
}

__device__ __forceinline__ void stg_cs_128(float4* p, float4 v) {
    // Streaming store: evict-first in L2 so output doesn't displace x/npool.
    asm volatile("st.global.cs.v4.f32 [%0], {%1,%2,%3,%4};"
                 :: "l"(p), "f"(v.x), "f"(v.y), "f"(v.z), "f"(v.w) : "memory");
}

__global__ __launch_bounds__(NTHREADS, 1)
void triple_transform_kernel(const float* __restrict__ x,
                             const int* __restrict__ move_p,
                             float* __restrict__ out) {
    extern __shared__ float s_pool[];           // HALF floats (200 KB)
    __shared__ float rs[32], rq[32];
    __shared__ float s_mu, s_inv;

    const int b = blockIdx.x;
    const float* xr = x + (size_t)b * L_LEN;

    int move = *move_p;
    move %= L_LEN; if (move < 0) move += L_LEN;

    float sum = 0.f, sumsq = 0.f;

    if ((move & 1) == 0) {
        // Even shift: each pooled pair is one aligned float2; wrap on float2 idx.
        const float2* xr2 = reinterpret_cast<const float2*>(xr);
        const int moff = move >> 1;
        const int JMAIN = (HALF / (UNROLL * NTHREADS)) * (UNROLL * NTHREADS); // 49152

        for (int j = threadIdx.x; j < JMAIN; j += UNROLL * NTHREADS) {
            int   jj[UNROLL];
            float2 v[UNROLL];
            float  np[UNROLL];
            #pragma unroll
            for (int u = 0; u < UNROLL; u++) {
                jj[u] = j + u * NTHREADS;
                int i = jj[u] - moff;
                if (i < 0) i += HALF;
                v[u]  = xr2[i];              // 4 independent LDG.64 in flight
                np[u] = g_npool[jj[u]];      // 4 independent L2-hit loads
            }
            #pragma unroll
            for (int u = 0; u < UNROLL; u++) {
                float p = 0.5f * (v[u].x + v[u].y) + np[u];
                s_pool[jj[u]] = p;
                sum   += p;
                sumsq += p * p;
            }
        }
        // Tail (848 elements)
        for (int j = JMAIN + threadIdx.x; j < HALF; j += NTHREADS) {
            int i = j - moff;
            if (i < 0) i += HALF;
            float2 v = xr2[i];
            float p = 0.5f * (v.x + v.y) + g_npool[j];
            s_pool[j] = p;
            sum += p;
            sumsq += p * p;
        }
    } else {
        // Generic odd-shift path (not hit for move=100, kept for correctness).
        for (int j = threadIdx.x; j < HALF; j += NTHREADS) {
            int i0 = 2 * j - move;
            if (i0 < 0) i0 += L_LEN;
            int i1 = i0 + 1;
            if (i1 >= L_LEN) i1 -= L_LEN;
            float p = 0.5f * (xr[i0] + xr[i1]) + g_npool[j];
            s_pool[j] = p;
            sum += p;
            sumsq += p * p;
        }
    }

    // Block reduction: warp shuffles, then warp 0 over 32 partials.
    #pragma unroll
    for (int o = 16; o; o >>= 1) {
        sum   += __shfl_down_sync(0xFFFFFFFFu, sum, o);
        sumsq += __shfl_down_sync(0xFFFFFFFFu, sumsq, o);
    }
    const int warp = threadIdx.x >> 5, lane = threadIdx.x & 31;
    if (lane == 0) { rs[warp] = sum; rq[warp] = sumsq; }
    __syncthreads();
    if (warp == 0) {
        float a = rs[lane];
        float q = rq[lane];
        #pragma unroll
        for (int o = 16; o; o >>= 1) {
            a += __shfl_down_sync(0xFFFFFFFFu, a, o);
            q += __shfl_down_sync(0xFFFFFFFFu, q, o);
        }
        if (lane == 0) {
            const float inv_n = 1.0f / (float)HALF;
            float mu  = a * inv_n;
            float var = fmaxf(q * inv_n - mu * mu, 0.f);
            s_mu  = mu;
            s_inv = rsqrtf(var);
        }
    }
    __syncthreads();

    // Write phase: two pooled values -> one float4 {v0,v0,v1,v1} (STG.128).
    // Read s_pool as float2 (LDS.64) to avoid 2-way bank conflicts.
    const float mu = s_mu, inv = s_inv;
    const float2* sp2 = reinterpret_cast<const float2*>(s_pool);
    float4* outr4 = reinterpret_cast<float4*>(out + (size_t)b * L_LEN);
    const int QMAIN = (QOUT / (UNROLL * NTHREADS)) * (UNROLL * NTHREADS);     // 24576

    for (int k = threadIdx.x; k < QMAIN; k += UNROLL * NTHREADS) {
        float2 pv[UNROLL];
        #pragma unroll
        for (int u = 0; u < UNROLL; u++)
            pv[u] = sp2[k + u * NTHREADS];
        #pragma unroll
        for (int u = 0; u < UNROLL; u++) {
            float v0 = (pv[u].x - mu) * inv;
            float v1 = (pv[u].y - mu) * inv;
            stg_cs_128(&outr4[k + u * NTHREADS], make_float4(v0, v0, v1, v1));
        }
    }
    for (int k = QMAIN + threadIdx.x; k < QOUT; k += NTHREADS) {
        float2 pv = sp2[k];
        float v0 = (pv.x - mu) * inv;
        float v1 = (pv.y - mu) * inv;
        stg_cs_128(&outr4[k], make_float4(v0, v0, v1, v1));
    }
}

extern "C" void kernel_launch(void* const* d_in, const int* in_sizes, int n_in,
                              void* d_out, int out_size) {
    const float* x     = (const float*)d_in[0];
    const float* noise = (const float*)d_in[1];
    const int*   move  = (const int*)d_in[2];
    float* out = (float*)d_out;

    cudaFuncSetAttribute(triple_transform_kernel,
                         cudaFuncAttributeMaxDynamicSharedMemorySize,
                         HALF * (int)sizeof(float));

    noise_pool_kernel<<<(HALF + 255) / 256, 256>>>(noise);
    triple_transform_kernel<<<B_ROWS, NTHREADS, HALF * sizeof(float)>>>(x, move, out);
}

// round 5
// speedup vs baseline: 1.3528x; 1.3528x over previous
#include <cuda_runtime.h>
#include <cstdint>
#include <math.h>

#define L_LEN     100000
#define B_ROWS    512
#define HALF      50000        // pooled elements per row
#define HALF_CTA  25000        // pooled elements per cluster-rank CTA
#define QOUT_CTA  12500        // float4 outputs per CTA
#define NOISE_STD 0.04f
#define NTHREADS  1024

// npool[j] = (noise[2j] + noise[2j+1]) * STD / 2. Row-invariant, L2-resident.
__device__ float g_npool[HALF];

__global__ void noise_pool_kernel(const float* __restrict__ noise) {
    int j = blockIdx.x * blockDim.x + threadIdx.x;
    if (j < HALF) {
        float2 n = reinterpret_cast<const float2*>(noise)[j];
        g_npool[j] = (n.x + n.y) * (0.5f * NOISE_STD);
    }
}

__device__ __forceinline__ unsigned int smem_u32(const void* p) {
    unsigned int a;
    asm("{ .reg .u64 t; cvta.to.shared.u64 t, %1; cvt.u32.u64 %0, t; }"
        : "=r"(a) : "l"(p));
    return a;
}

// One row per 2-CTA cluster. Each CTA owns 25000 pooled elems in 100KB smem
// -> 2 CTAs/SM -> 64 warps/SM (full occupancy), double the in-flight loads.
__global__ __launch_bounds__(NTHREADS, 2) __cluster_dims__(2, 1, 1)
void triple_transform_kernel(const float* __restrict__ x,
                             const int* __restrict__ move_p,
                             float* __restrict__ out) {
    extern __shared__ float s_pool[];              // HALF_CTA floats (100 KB)
    __shared__ float rs[32], rq[32];
    __shared__ float s_part[2];                    // this CTA's {sum, sumsq}
    __shared__ float s_mu, s_inv;

    unsigned int rank;
    asm("mov.u32 %0, %%cluster_ctarank;" : "=r"(rank));
    const int b = blockIdx.x >> 1;                 // row = cluster id
    const int jbase = (int)rank * HALF_CTA;        // global pooled offset

    const float* xr = x + (size_t)b * L_LEN;

    int move = *move_p;
    move %= L_LEN; if (move < 0) move += L_LEN;

    float sum = 0.f, sumsq = 0.f;

    if ((move & 1) == 0) {
        // Even shift: one aligned float2 per pooled pair; wrap on float2 index.
        const float2* xr2 = reinterpret_cast<const float2*>(xr);
        const int moff = move >> 1;
        for (int t = threadIdx.x; t < HALF_CTA; t += NTHREADS) {
            int j = jbase + t;
            int i = j - moff;
            if (i < 0) i += HALF;
            float2 v = xr2[i];
            float p = 0.5f * (v.x + v.y) + g_npool[j];
            s_pool[t] = p;
            sum += p;
            sumsq += p * p;
        }
    } else {
        // Generic odd-shift path (not hit for move=100).
        for (int t = threadIdx.x; t < HALF_CTA; t += NTHREADS) {
            int j = jbase + t;
            int i0 = 2 * j - move;
            if (i0 < 0) i0 += L_LEN;
            int i1 = i0 + 1;
            if (i1 >= L_LEN) i1 -= L_LEN;
            float p = 0.5f * (xr[i0] + xr[i1]) + g_npool[j];
            s_pool[t] = p;
            sum += p;
            sumsq += p * p;
        }
    }

    // Local block reduction.
    #pragma unroll
    for (int o = 16; o; o >>= 1) {
        sum   += __shfl_down_sync(0xFFFFFFFFu, sum, o);
        sumsq += __shfl_down_sync(0xFFFFFFFFu, sumsq, o);
    }
    const int warp = threadIdx.x >> 5, lane = threadIdx.x & 31;
    if (lane == 0) { rs[warp] = sum; rq[warp] = sumsq; }
    __syncthreads();
    if (warp == 0) {
        float a = rs[lane], q = rq[lane];
        #pragma unroll
        for (int o = 16; o; o >>= 1) {
            a += __shfl_down_sync(0xFFFFFFFFu, a, o);
            q += __shfl_down_sync(0xFFFFFFFFu, q, o);
        }
        if (lane == 0) { s_part[0] = a; s_part[1] = q; }
    }
    __syncthreads();

    // Exchange partials with the peer CTA via DSMEM.
    asm volatile("barrier.cluster.arrive.aligned;" ::: "memory");
    asm volatile("barrier.cluster.wait.aligned;"   ::: "memory");

    if (threadIdx.x == 0) {
        unsigned int myaddr = smem_u32(&s_part[0]);
        unsigned int peeraddr;
        unsigned int peer = rank ^ 1u;
        asm("mapa.shared::cluster.u32 %0, %1, %2;"
            : "=r"(peeraddr) : "r"(myaddr), "r"(peer));
        float ps, pq;
        asm volatile("ld.shared::cluster.f32 %0, [%1];"     : "=f"(ps) : "r"(peeraddr));
        asm volatile("ld.shared::cluster.f32 %0, [%1 + 4];" : "=f"(pq) : "r"(peeraddr));
        const float inv_n = 1.0f / (float)HALF;
        float a = s_part[0] + ps;
        float q = s_part[1] + pq;
        float mu  = a * inv_n;
        float var = fmaxf(q * inv_n - mu * mu, 0.f);
        s_mu  = mu;
        s_inv = rsqrtf(var);
    }
    __syncthreads();

    // Write phase: float2 smem read -> float4 {v0,v0,v1,v1} global store.
    const float mu = s_mu, inv = s_inv;
    const float2* sp2 = reinterpret_cast<const float2*>(s_pool);
    float4* outr4 = reinterpret_cast<float4*>(out + (size_t)b * L_LEN) + (size_t)rank * QOUT_CTA;
    for (int k = threadIdx.x; k < QOUT_CTA; k += NTHREADS) {
        float2 pv = sp2[k];
        float v0 = (pv.x - mu) * inv;
        float v1 = (pv.y - mu) * inv;
        outr4[k] = make_float4(v0, v0, v1, v1);
    }

    // No CTA may exit while its peer might still DSMEM-read s_part.
    asm volatile("barrier.cluster.arrive.aligned;" ::: "memory");
    asm volatile("barrier.cluster.wait.aligned;"   ::: "memory");
}

extern "C" void kernel_launch(void* const* d_in, const int* in_sizes, int n_in,
                              void* d_out, int out_size) {
    const float* x     = (const float*)d_in[0];
    const float* noise = (const float*)d_in[1];
    const int*   move  = (const int*)d_in[2];
    float* out = (float*)d_out;

    cudaFuncSetAttribute(triple_transform_kernel,
                         cudaFuncAttributeMaxDynamicSharedMemorySize,
                         HALF_CTA * (int)sizeof(float));

    noise_pool_kernel<<<(HALF + 255) / 256, 256>>>(noise);
    triple_transform_kernel<<<2 * B_ROWS, NTHREADS, HALF_CTA * sizeof(float)>>>(x, move, out);
}